// round 17
// baseline (speedup 1.0000x reference)
#include <cuda_runtime.h>
#include <cuda_bf16.h>
#include <cuda_fp16.h>
#include <math_constants.h>
#include <cstdint>
#include <cstring>

#define BATCH 4
#define SEQ   2048
#define CDIM  1024
#define NHEAD 16
#define HDIM  64
#define N3C   3072

__device__ float  g_Q[BATCH * NHEAD * SEQ * HDIM];
__device__ float  g_K[BATCH * NHEAD * SEQ * HDIM];
__device__ __half g_Vh[BATCH * NHEAD * HDIM * SEQ];   // [B,H,D,T] f16
__device__ float  g_O[BATCH * NHEAD * SEQ * HDIM];
// pre-rounded tf32-bit copies. Weights are TRANSPOSED [n][k] with per-k8
// permutation perm(l) = ((l&3)<<1)|(l>>2) applied to the k index.
__device__ float g_Xr[BATCH * SEQ * CDIM];        // [m][k] plain
__device__ float g_Wqr[N3C * CDIM];               // [n][k] permuted
__device__ float g_Wor[CDIM * CDIM];              // [n][k] permuted

// ---------------------------------------------------------------------------
// helpers
// ---------------------------------------------------------------------------
__device__ __forceinline__ uint32_t f2tf32(float f) {
    uint32_t r;
    asm("cvt.rna.tf32.f32 %0, %1;" : "=r"(r) : "f"(f));
    return r;
}

__device__ __forceinline__ float roundtf(float f) {
    return __uint_as_float(f2tf32(f));
}

__device__ __forceinline__ uint32_t h2u(__half2 h) {
    uint32_t r;
    memcpy(&r, &h, 4);
    return r;
}

__device__ __forceinline__ void cp16(void* smem, const void* gmem) {
    uint32_t s = (uint32_t)__cvta_generic_to_shared(smem);
    asm volatile("cp.async.cg.shared.global [%0], [%1], 16;"
                 :: "r"(s), "l"(gmem) : "memory");
}
#define CP_COMMIT() asm volatile("cp.async.commit_group;" ::: "memory")
#define CP_WAIT0()  asm volatile("cp.async.wait_group 0;" ::: "memory")
#define CP_WAIT1()  asm volatile("cp.async.wait_group 1;" ::: "memory")

__device__ __forceinline__ void mma_tf32(float c[4],
                                         const uint32_t a[4],
                                         uint32_t b0, uint32_t b1) {
    asm volatile(
        "mma.sync.aligned.m16n8k8.row.col.f32.tf32.tf32.f32 "
        "{%0,%1,%2,%3}, {%4,%5,%6,%7}, {%8,%9}, {%0,%1,%2,%3};\n"
        : "+f"(c[0]), "+f"(c[1]), "+f"(c[2]), "+f"(c[3])
        : "r"(a[0]), "r"(a[1]), "r"(a[2]), "r"(a[3]),
          "r"(b0), "r"(b1));
}

__device__ __forceinline__ void mma_f16(float c[4],
                                        const uint32_t a[4],
                                        uint32_t b0, uint32_t b1) {
    asm volatile(
        "mma.sync.aligned.m16n8k16.row.col.f32.f16.f16.f32 "
        "{%0,%1,%2,%3}, {%4,%5,%6,%7}, {%8,%9}, {%0,%1,%2,%3};\n"
        : "+f"(c[0]), "+f"(c[1]), "+f"(c[2]), "+f"(c[3])
        : "r"(a[0]), "r"(a[1]), "r"(a[2]), "r"(a[3]),
          "r"(b0), "r"(b1));
}

#define ASTR 20    // A smem row stride (floats): bases 20g mod 32 all distinct
#define BSTR 24    // B smem row stride (floats): LDS.64 bank bases {0,24,16,8}

// ---------------------------------------------------------------------------
// Kernel 0a: tf32 pre-rounding (X, plain layout)
// ---------------------------------------------------------------------------
__global__ __launch_bounds__(256) void round_kernel(
    const float* __restrict__ src, float* __restrict__ dst, int n4)
{
    for (int i = blockIdx.x * blockDim.x + threadIdx.x; i < n4;
         i += gridDim.x * blockDim.x) {
        float4 v = ((const float4*)src)[i];
        v.x = roundtf(v.x); v.y = roundtf(v.y);
        v.z = roundtf(v.z); v.w = roundtf(v.w);
        ((float4*)dst)[i] = v;
    }
}

// ---------------------------------------------------------------------------
// Kernel 0b: weight transpose + per-k8 permutation + tf32 rounding.
// src [K][N] row-major -> dst [N][K], dst k-index permuted within each k8.
// ---------------------------------------------------------------------------
__global__ __launch_bounds__(256) void transpose_perm(
    const float* __restrict__ src, float* __restrict__ dst, int K, int N)
{
    __shared__ float tile[32][33];
    const int kb = blockIdx.y * 32;
    const int nb = blockIdx.x * 32;
    const int tx = threadIdx.x;          // 0..31
    const int ty = threadIdx.y;          // 0..7

    #pragma unroll
    for (int i = ty; i < 32; i += 8)
        tile[i][tx] = src[(size_t)(kb + i) * N + nb + tx];
    __syncthreads();

    #pragma unroll
    for (int i = ty; i < 32; i += 8) {
        const int n = nb + i;
        const int k = tx;
        const int kp = (k & ~7) | (((k & 3) << 1) | ((k >> 2) & 1));
        dst[(size_t)n * K + kb + kp] = roundtf(tile[k][i]);
    }
}

// ---------------------------------------------------------------------------
// Kernel 1: QKV GEMM, tf32 mma, 128x128 CTA tile, BK=16, 256 threads,
// 8 warps (4Mx2N), 32x64 per warp. A staged [m][k]; B staged [n][k]
// (pre-transposed + k8-permuted) so each B fragment is ONE LDS.64.
// ---------------------------------------------------------------------------
__global__ __launch_bounds__(256, 3) void qkv_gemm(
    const float* __restrict__ X,    // [8192, 1024]  pre-rounded
    const float* __restrict__ Wt,   // [3072, 1024]  transposed+permuted
    const float* __restrict__ bias) // [3072]
{
    __shared__ float As[2][128][ASTR];   // [m][k]
    __shared__ float Bs[2][128][BSTR];   // [n][k] (permuted within k8)

    const int tid = threadIdx.x;
    const int wid = tid >> 5;
    const int lane = tid & 31;
    const int g = lane >> 2;
    const int tig = lane & 3;
    const int warp_m = wid >> 1;
    const int warp_n = wid & 1;

    const int bm = blockIdx.y * 128;
    const int bn = blockIdx.x * 128;

    const int ar = tid >> 2;
    const int ac = (tid & 3) * 4;
    const int bnr = tid >> 1;            // 0..127
    const int bko = (tid & 1) * 8;       // 0 or 8

    const float* Ap0 = X + (size_t)(bm + ar) * CDIM + ac;
    const float* Ap1 = X + (size_t)(bm + ar + 64) * CDIM + ac;
    const float* BpT = Wt + (size_t)(bn + bnr) * CDIM;

    float acc[2][8][4];
    #pragma unroll
    for (int mt = 0; mt < 2; mt++)
        #pragma unroll
        for (int nt = 0; nt < 8; nt++)
            #pragma unroll
            for (int i = 0; i < 4; i++) acc[mt][nt][i] = 0.f;

    auto issue_cp = [&](int buf, int k0) {
        cp16(&As[buf][ar][ac],          Ap0 + k0);
        cp16(&As[buf][ar + 64][ac],     Ap1 + k0);
        cp16(&Bs[buf][bnr][bko],        BpT + k0 + bko);
        cp16(&Bs[buf][bnr][bko + 4],    BpT + k0 + bko + 4);
        CP_COMMIT();
    };

    issue_cp(0, 0);
    CP_WAIT0();
    __syncthreads();

    const int am = warp_m * 32;
    const int an = warp_n * 64;

    int cur = 0;
    for (int k0 = 0; k0 < CDIM; k0 += 16) {
        const bool has_next = (k0 + 16) < CDIM;
        if (has_next) issue_cp(cur ^ 1, k0 + 16);

        #pragma unroll
        for (int kk = 0; kk < 16; kk += 8) {
            uint32_t Af[2][4];
            uint2 Bf[8];
            #pragma unroll
            for (int mt = 0; mt < 2; mt++) {
                const int m0 = am + mt * 16;
                Af[mt][0] = __float_as_uint(As[cur][m0 + g][kk + tig]);
                Af[mt][1] = __float_as_uint(As[cur][m0 + g + 8][kk + tig]);
                Af[mt][2] = __float_as_uint(As[cur][m0 + g][kk + tig + 4]);
                Af[mt][3] = __float_as_uint(As[cur][m0 + g + 8][kk + tig + 4]);
            }
            #pragma unroll
            for (int nt = 0; nt < 8; nt++)
                Bf[nt] = *(const uint2*)&Bs[cur][an + nt * 8 + g][kk + tig * 2];
            #pragma unroll
            for (int mt = 0; mt < 2; mt++)
                #pragma unroll
                for (int nt = 0; nt < 8; nt++)
                    mma_tf32(acc[mt][nt], Af[mt], Bf[nt].x, Bf[nt].y);
        }

        if (has_next) {
            CP_WAIT0();
            __syncthreads();
            cur ^= 1;
        }
    }

    // Epilogue: Q scaled+rounded; K rounded; V -> f16 in [B,H,D,T].
    #pragma unroll
    for (int mt = 0; mt < 2; mt++) {
        #pragma unroll
        for (int half = 0; half < 2; half++) {
            const int row = bm + am + mt * 16 + g + half * 8;
            const int bb = row >> 11;
            const int t  = row & 2047;
            #pragma unroll
            for (int nt = 0; nt < 8; nt++) {
                const int col = bn + an + nt * 8 + tig * 2;
                float v0 = acc[mt][nt][half * 2 + 0] + bias[col];
                float v1 = acc[mt][nt][half * 2 + 1] + bias[col + 1];
                const int part = col >> 10;      // 0=Q 1=K 2=V
                const int cc = col & 1023;
                const int h = cc >> 6;
                const int d = cc & 63;
                if (part == 2) {
                    __half* vd = g_Vh +
                        ((size_t)(bb * NHEAD + h) * HDIM + d) * SEQ + t;
                    vd[0]   = __float2half(v0);
                    vd[SEQ] = __float2half(v1);
                } else {
                    if (part == 0) {
                        v0 = roundtf(v0 * 0.125f);
                        v1 = roundtf(v1 * 0.125f);
                    } else {
                        v0 = roundtf(v0);
                        v1 = roundtf(v1);
                    }
                    float* dst = (part == 0) ? g_Q : g_K;
                    const int idx = ((bb * NHEAD + h) * SEQ + t) * HDIM + d;
                    *(float2*)&dst[idx] = make_float2(v0, v1);
                }
            }
        }
    }
}

// ---------------------------------------------------------------------------
// Kernel 2: tensor-core causal flash attention, cp.async double-buffered
// K/V staging. minBlocksPerSM=2 to cap regs at 128 (occupancy lift).
// ---------------------------------------------------------------------------
#define KSTRIDE 68                     // floats per key row (272B)
#define VSTRIDE 72                     // halves per dim row (144B)
#define KS_U32  (64 * KSTRIDE)
#define VS_H    (64 * VSTRIDE)
#define ATTN_SMEM (2 * KS_U32 * 4 + 2 * VS_H * 2)   // 53248 B

__global__ __launch_bounds__(256, 2) void attn_kernel()
{
    extern __shared__ uint32_t dynsmem[];
    uint32_t* KsB = dynsmem;
    __half*  VsB = (__half*)(dynsmem + 2 * KS_U32);

    const int bh  = blockIdx.y;
    const int qt  = (SEQ / 128 - 1) - blockIdx.x;
    const int tid = threadIdx.x;
    const int wid = tid >> 5;
    const int lane = tid & 31;
    const int g   = lane >> 2;
    const int tig = lane & 3;

    const int qbase = qt * 128;
    const int wbase = qbase + wid * 16;
    const int row0  = wbase + g;
    const int row1  = row0 + 8;

    const float*  Qb = g_Q + (size_t)bh * SEQ * HDIM;
    const float*  Kb = g_K + (size_t)bh * SEQ * HDIM;
    const __half* Vb = g_Vh + (size_t)bh * HDIM * SEQ;

    uint32_t qf[8][4];
    #pragma unroll
    for (int kt8 = 0; kt8 < 8; kt8++) {
        qf[kt8][0] = __float_as_uint(Qb[(size_t)row0 * HDIM + kt8 * 8 + tig]);
        qf[kt8][1] = __float_as_uint(Qb[(size_t)row1 * HDIM + kt8 * 8 + tig]);
        qf[kt8][2] = __float_as_uint(Qb[(size_t)row0 * HDIM + kt8 * 8 + tig + 4]);
        qf[kt8][3] = __float_as_uint(Qb[(size_t)row1 * HDIM + kt8 * 8 + tig + 4]);
    }

    float of[8][4];
    #pragma unroll
    for (int dt = 0; dt < 8; dt++)
        #pragma unroll
        for (int i = 0; i < 4; i++) of[dt][i] = 0.f;

    float m0 = -CUDART_INF_F, m1 = -CUDART_INF_F;
    float l0 = 0.f, l1 = 0.f;

    const int ktmax = (qbase + 127) >> 6;

    auto stage_tile = [&](int buf, int kt) {
        uint32_t* Kd = KsB + buf * KS_U32;
        __half*   Vd = VsB + buf * VS_H;
        #pragma unroll
        for (int i = 0; i < 4; i++) {
            const int c = tid + i * 256;
            const int key = c >> 4;
            const int off = (c & 15) * 4;
            cp16(Kd + key * KSTRIDE + off,
                 Kb + (size_t)(kt * 64 + key) * HDIM + off);
        }
        #pragma unroll
        for (int i = 0; i < 2; i++) {
            const int c = tid + i * 256;
            const int dim = c >> 3;
            const int ko  = (c & 7) * 8;
            cp16(Vd + dim * VSTRIDE + ko,
                 Vb + (size_t)dim * SEQ + kt * 64 + ko);
        }
        CP_COMMIT();
    };

    stage_tile(0, 0);

    int cur = 0;
    for (int kt = 0; kt <= ktmax; kt++) {
        const bool has_next = kt < ktmax;
        if (has_next) stage_tile(cur ^ 1, kt + 1);
        if (has_next) { CP_WAIT1(); } else { CP_WAIT0(); }
        __syncthreads();

        if (kt * 64 <= wbase + 15) {
            const uint32_t* Kd = KsB + cur * KS_U32;
            const __half*   Vd = VsB + cur * VS_H;

            float sf[8][4];
            #pragma unroll
            for (int nt = 0; nt < 8; nt++) {
                sf[nt][0] = sf[nt][1] = sf[nt][2] = sf[nt][3] = 0.f;
                const int kr = nt * 8 + g;
                #pragma unroll
                for (int kt8 = 0; kt8 < 8; kt8++) {
                    uint32_t b0 = Kd[kr * KSTRIDE + kt8 * 8 + tig];
                    uint32_t b1 = Kd[kr * KSTRIDE + kt8 * 8 + tig + 4];
                    mma_tf32(sf[nt], qf[kt8], b0, b1);
                }
            }

            const int colbase = kt * 64;
            if (colbase + 63 > wbase) {
                #pragma unroll
                for (int nt = 0; nt < 8; nt++) {
                    const int c = colbase + nt * 8 + tig * 2;
                    if (c     > row0) sf[nt][0] = -CUDART_INF_F;
                    if (c + 1 > row0) sf[nt][1] = -CUDART_INF_F;
                    if (c     > row1) sf[nt][2] = -CUDART_INF_F;
                    if (c + 1 > row1) sf[nt][3] = -CUDART_INF_F;
                }
            }

            float t0 = -CUDART_INF_F, t1 = -CUDART_INF_F;
            #pragma unroll
            for (int nt = 0; nt < 8; nt++) {
                t0 = fmaxf(t0, fmaxf(sf[nt][0], sf[nt][1]));
                t1 = fmaxf(t1, fmaxf(sf[nt][2], sf[nt][3]));
            }
            t0 = fmaxf(t0, __shfl_xor_sync(0xffffffffu, t0, 1));
            t0 = fmaxf(t0, __shfl_xor_sync(0xffffffffu, t0, 2));
            t1 = fmaxf(t1, __shfl_xor_sync(0xffffffffu, t1, 1));
            t1 = fmaxf(t1, __shfl_xor_sync(0xffffffffu, t1, 2));

            const float mn0 = fmaxf(m0, t0);
            const float mn1 = fmaxf(m1, t1);
            const float al0 = __expf(m0 - mn0);
            const float al1 = __expf(m1 - mn1);
            m0 = mn0; m1 = mn1;
            l0 *= al0; l1 *= al1;
            #pragma unroll
            for (int dt = 0; dt < 8; dt++) {
                of[dt][0] *= al0; of[dt][1] *= al0;
                of[dt][2] *= al1; of[dt][3] *= al1;
            }

            uint32_t pa[4][4];
            #pragma unroll
            for (int nt = 0; nt < 8; nt++) {
                const float p0 = __expf(sf[nt][0] - m0);
                const float p1 = __expf(sf[nt][1] - m0);
                const float p2 = __expf(sf[nt][2] - m1);
                const float p3 = __expf(sf[nt][3] - m1);
                l0 += p0 + p1;
                l1 += p2 + p3;
                const uint32_t lo = h2u(__floats2half2_rn(p0, p1));
                const uint32_t hi = h2u(__floats2half2_rn(p2, p3));
                const int kc  = nt >> 1;
                if ((nt & 1) == 0) { pa[kc][0] = lo; pa[kc][1] = hi; }
                else               { pa[kc][2] = lo; pa[kc][3] = hi; }
            }

            #pragma unroll
            for (int dt = 0; dt < 8; dt++) {
                const int dr = dt * 8 + g;
                #pragma unroll
                for (int kc = 0; kc < 4; kc++) {
                    uint32_t b0 = *(const uint32_t*)&Vd[dr * VSTRIDE + kc * 16 + tig * 2];
                    uint32_t b1 = *(const uint32_t*)&Vd[dr * VSTRIDE + kc * 16 + tig * 2 + 8];
                    mma_f16(of[dt], pa[kc], b0, b1);
                }
            }
        }

        __syncthreads();
        cur ^= 1;
    }

    l0 += __shfl_xor_sync(0xffffffffu, l0, 1);
    l0 += __shfl_xor_sync(0xffffffffu, l0, 2);
    l1 += __shfl_xor_sync(0xffffffffu, l1, 1);
    l1 += __shfl_xor_sync(0xffffffffu, l1, 2);
    const float inv0 = 1.0f / l0;
    const float inv1 = 1.0f / l1;

    float* Ob = g_O + (size_t)bh * SEQ * HDIM;
    #pragma unroll
    for (int dt = 0; dt < 8; dt++) {
        const int col = dt * 8 + tig * 2;
        *(float2*)&Ob[(size_t)row0 * HDIM + col] =
            make_float2(roundtf(of[dt][0] * inv0), roundtf(of[dt][1] * inv0));
        *(float2*)&Ob[(size_t)row1 * HDIM + col] =
            make_float2(roundtf(of[dt][2] * inv1), roundtf(of[dt][3] * inv1));
    }
}

// ---------------------------------------------------------------------------
// Kernel 3: output projection; A = g_O (pre-rounded), B = g_Wor
// (transposed+permuted). Same LDS.64 B fragments.
// ---------------------------------------------------------------------------
__global__ __launch_bounds__(256, 3) void out_gemm(
    const float* __restrict__ Wt,   // [1024, 1024] transposed+permuted
    const float* __restrict__ bias, // [1024]
    float* __restrict__ out)        // [8192, 1024]
{
    __shared__ float As[2][128][ASTR];
    __shared__ float Bs[2][128][BSTR];

    const int tid = threadIdx.x;
    const int wid = tid >> 5;
    const int lane = tid & 31;
    const int g = lane >> 2;
    const int tig = lane & 3;
    const int warp_m = wid >> 1;
    const int warp_n = wid & 1;

    const int bm = blockIdx.y * 128;
    const int bn = blockIdx.x * 128;

    const int ar = tid >> 2;
    const int ac = (tid & 3) * 4;
    const int bnr = tid >> 1;
    const int bko = (tid & 1) * 8;

    const float* BpT = Wt + (size_t)(bn + bnr) * CDIM;

    const int row0g = bm + ar;
    const int row1g = bm + ar + 64;
    const int bb0 = row0g >> 11, t0r = row0g & 2047;
    const int bb1 = row1g >> 11, t1r = row1g & 2047;

    float acc[2][8][4];
    #pragma unroll
    for (int mt = 0; mt < 2; mt++)
        #pragma unroll
        for (int nt = 0; nt < 8; nt++)
            #pragma unroll
            for (int i = 0; i < 4; i++) acc[mt][nt][i] = 0.f;

    auto issue_cp = [&](int buf, int k0) {
        const int k = k0 + ac;
        const int h = k >> 6;
        const int d = k & 63;
        cp16(&As[buf][ar][ac],
             &g_O[((bb0 * NHEAD + h) * SEQ + t0r) * HDIM + d]);
        cp16(&As[buf][ar + 64][ac],
             &g_O[((bb1 * NHEAD + h) * SEQ + t1r) * HDIM + d]);
        cp16(&Bs[buf][bnr][bko],     BpT + k0 + bko);
        cp16(&Bs[buf][bnr][bko + 4], BpT + k0 + bko + 4);
        CP_COMMIT();
    };

    issue_cp(0, 0);
    CP_WAIT0();
    __syncthreads();

    const int am = warp_m * 32;
    const int an = warp_n * 64;

    int cur = 0;
    for (int k0 = 0; k0 < CDIM; k0 += 16) {
        const bool has_next = (k0 + 16) < CDIM;
        if (has_next) issue_cp(cur ^ 1, k0 + 16);

        #pragma unroll
        for (int kk = 0; kk < 16; kk += 8) {
            uint32_t Af[2][4];
            uint2 Bf[8];
            #pragma unroll
            for (int mt = 0; mt < 2; mt++) {
                const int m0 = am + mt * 16;
                Af[mt][0] = __float_as_uint(As[cur][m0 + g][kk + tig]);
                Af[mt][1] = __float_as_uint(As[cur][m0 + g + 8][kk + tig]);
                Af[mt][2] = __float_as_uint(As[cur][m0 + g][kk + tig + 4]);
                Af[mt][3] = __float_as_uint(As[cur][m0 + g + 8][kk + tig + 4]);
            }
            #pragma unroll
            for (int nt = 0; nt < 8; nt++)
                Bf[nt] = *(const uint2*)&Bs[cur][an + nt * 8 + g][kk + tig * 2];
            #pragma unroll
            for (int mt = 0; mt < 2; mt++)
                #pragma unroll
                for (int nt = 0; nt < 8; nt++)
                    mma_tf32(acc[mt][nt], Af[mt], Bf[nt].x, Bf[nt].y);
        }

        if (has_next) {
            CP_WAIT0();
            __syncthreads();
            cur ^= 1;
        }
    }

    #pragma unroll
    for (int mt = 0; mt < 2; mt++) {
        #pragma unroll
        for (int half = 0; half < 2; half++) {
            const int row = bm + am + mt * 16 + g + half * 8;
            #pragma unroll
            for (int nt = 0; nt < 8; nt++) {
                const int col = bn + an + nt * 8 + tig * 2;
                float v0 = acc[mt][nt][half * 2 + 0] + bias[col];
                float v1 = acc[mt][nt][half * 2 + 1] + bias[col + 1];
                *(float2*)&out[(size_t)row * CDIM + col] = make_float2(v0, v1);
            }
        }
    }
}

// ---------------------------------------------------------------------------
extern "C" void kernel_launch(void* const* d_in, const int* in_sizes, int n_in,
                              void* d_out, int out_size)
{
    const float* x     = (const float*)d_in[0];
    const float* W_qkv = (const float*)d_in[1];
    const float* b_qkv = (const float*)d_in[2];
    const float* W_out = (const float*)d_in[3];
    const float* b_out = (const float*)d_in[4];
    float* out = (float*)d_out;

    float *d_Xr, *d_Wqr, *d_Wor;
    cudaGetSymbolAddress((void**)&d_Xr,  g_Xr);
    cudaGetSymbolAddress((void**)&d_Wqr, g_Wqr);
    cudaGetSymbolAddress((void**)&d_Wor, g_Wor);

    // Idempotent; called every invocation (no static guards allowed).
    cudaFuncSetAttribute(attn_kernel,
                         cudaFuncAttributeMaxDynamicSharedMemorySize,
                         ATTN_SMEM);

    // 0) prepass: round X; transpose+permute+round weights
    round_kernel<<<2048, 256>>>(x, d_Xr, (BATCH * SEQ * CDIM) / 4);
    transpose_perm<<<dim3(N3C / 32, CDIM / 32), dim3(32, 8)>>>(
        W_qkv, d_Wqr, CDIM, N3C);
    transpose_perm<<<dim3(CDIM / 32, CDIM / 32), dim3(32, 8)>>>(
        W_out, d_Wor, CDIM, CDIM);

    // 1) QKV projection
    qkv_gemm<<<dim3(N3C / 128, (BATCH * SEQ) / 128), 256>>>(d_Xr, d_Wqr, b_qkv);

    // 2) causal flash attention (pipelined staging)
    attn_kernel<<<dim3(SEQ / 128, BATCH * NHEAD), 256, ATTN_SMEM>>>();

    // 3) output projection
    out_gemm<<<dim3(CDIM / 128, (BATCH * SEQ) / 128), 256>>>(d_Wor, b_out, out);
}